// round 17
// baseline (speedup 1.0000x reference)
#include <cuda_runtime.h>
#include <cuda_fp16.h>
#include <cstdint>
#include <math.h>

// ---------------------------------------------------------------------------
// DiT block: fp16 mma.sync GEMMs (128x128, BK=64, cp.async 3-stage, ldmatrix,
// 2 CTAs/SM) + cp.async flash attention (register-resident P, LDSM K/V).
// B=4, N=1024, H=1024, heads=16, d=64, D_FF=4096
// ---------------------------------------------------------------------------

#define Bsz 4
#define Ntok 1024
#define Hdim 1024
#define NH 16
#define HD 64
#define DFF 4096
#define ROWS (Bsz * Ntok)      // 4096
#define CM_STRIDE (6 * Hdim)   // 6144

// ------------------------- scratch (device globals) ------------------------
__device__ float    g_cm[Bsz * CM_STRIDE];
__device__ float    g_cpart[Bsz * 8 * CM_STRIDE];
__device__ __half   g_xmh[ROWS * Hdim];
__device__ __half   g_qkvh[ROWS * 3 * Hdim];
__device__ __half   g_attnh[ROWS * Hdim];
__device__ float    g_x2[ROWS * Hdim];
__device__ __half   g_xm2h[ROWS * Hdim];
__device__ __half   g_hidh[ROWS * DFF];
// plain half weights [K][N]
__device__ __half   g_wqkvH[Hdim * 3 * Hdim];
__device__ __half   g_w1H[Hdim * DFF];
__device__ __half   g_w2H[DFF * Hdim];
__device__ __half   g_wpH[Hdim * Hdim];

// ------------------------- helpers -----------------------------------------
__device__ __forceinline__ unsigned f2h2(float a, float b) {
    __half2 h = __floats2half2_rn(a, b);
    return *(unsigned*)&h;
}

__device__ __forceinline__ uint32_t smem_u32(const void* p) {
    uint32_t a;
    asm("{ .reg .u64 t; cvta.to.shared.u64 t, %1; cvt.u32.u64 %0, t; }"
        : "=r"(a) : "l"(p));
    return a;
}

__device__ __forceinline__ void mma_f16(float* d, const unsigned* a, const unsigned* b) {
    asm volatile(
        "mma.sync.aligned.m16n8k16.row.col.f32.f16.f16.f32 "
        "{%0,%1,%2,%3},{%4,%5,%6,%7},{%8,%9},{%0,%1,%2,%3};\n"
        : "+f"(d[0]), "+f"(d[1]), "+f"(d[2]), "+f"(d[3])
        : "r"(a[0]), "r"(a[1]), "r"(a[2]), "r"(a[3]), "r"(b[0]), "r"(b[1]));
}

#define LDSM4(r0, r1, r2, r3, a) \
    asm volatile("ldmatrix.sync.aligned.m8n8.x4.shared.b16 {%0,%1,%2,%3}, [%4];" \
                 : "=r"(r0), "=r"(r1), "=r"(r2), "=r"(r3) : "r"(a))
#define LDSM4T(r0, r1, r2, r3, a) \
    asm volatile("ldmatrix.sync.aligned.m8n8.x4.trans.shared.b16 {%0,%1,%2,%3}, [%4];" \
                 : "=r"(r0), "=r"(r1), "=r"(r2), "=r"(r3) : "r"(a))

#define CP_ASYNC16(saddr, gptr) \
    asm volatile("cp.async.cg.shared.global [%0], [%1], 16;" \
                 :: "r"(saddr), "l"(gptr) : "memory")
#define CP_COMMIT() asm volatile("cp.async.commit_group;" ::: "memory")
#define CP_WAIT1()  asm volatile("cp.async.wait_group 1;" ::: "memory")

// ------------------------- fused weight -> half (MLP=2) ---------------------
#define WQKV_F4 (3 * Hdim * Hdim / 4)
#define W1_F4   (Hdim * DFF / 4)
#define W2_F4   (DFF * Hdim / 4)
#define WP_F4   (Hdim * Hdim / 4)
#define TOT_F4  (WQKV_F4 + W1_F4 + W2_F4 + WP_F4)
#define HALF_F4 (TOT_F4 / 2)

__device__ __forceinline__ void whalf_one(size_t i,
                                          const float* wqkv, const float* w1,
                                          const float* w2, const float* wp,
                                          __half* oqkv, __half* o1,
                                          __half* o2, __half* op)
{
    const float* src;
    __half* dst;
    size_t off = i;
    if (off < WQKV_F4)                       { src = wqkv; dst = oqkv; }
    else if ((off -= WQKV_F4) < W1_F4)       { src = w1;   dst = o1;   }
    else if ((off -= W1_F4) < W2_F4)         { src = w2;   dst = o2;   }
    else { off -= W2_F4;                       src = wp;   dst = op;   }
    float4 v = *(const float4*)(src + off * 4);
    uint2 h = make_uint2(f2h2(v.x, v.y), f2h2(v.z, v.w));
    *(uint2*)(dst + off * 4) = h;
}

__global__ void whalf_all_kernel(const float* __restrict__ wqkv,
                                 const float* __restrict__ w1,
                                 const float* __restrict__ w2,
                                 const float* __restrict__ wp,
                                 __half* __restrict__ oqkv,
                                 __half* __restrict__ o1,
                                 __half* __restrict__ o2,
                                 __half* __restrict__ op)
{
    size_t i = (size_t)blockIdx.x * 256 + threadIdx.x;
    whalf_one(i, wqkv, w1, w2, wp, oqkv, o1, o2, op);
    whalf_one(i + HALF_F4, wqkv, w1, w2, wp, oqkv, o1, o2, op);
}

// ------------------------- cond modulation (split-K, float4) ----------------
__global__ void cond_part_kernel(const float* __restrict__ c,
                                 const float* __restrict__ w,
                                 float* __restrict__ part)
{
    // grid (6, 4, 8); thread handles 4 consecutive j
    int j4 = blockIdx.x * 256 + threadIdx.x;   // float4 index within 1536
    int b = blockIdx.y, kc = blockIdx.z;
    __shared__ float sc[128];
    if (threadIdx.x < 128) {
        float t = c[b * Hdim + kc * 128 + threadIdx.x];
        sc[threadIdx.x] = t / (1.0f + expf(-t));
    }
    __syncthreads();
    float4 acc = make_float4(0.f, 0.f, 0.f, 0.f);
    const float4* wp = (const float4*)(w + (size_t)(kc * 128) * CM_STRIDE) + j4;
    #pragma unroll 8
    for (int k = 0; k < 128; k++) {
        float4 wv = wp[(size_t)k * (CM_STRIDE / 4)];
        float s = sc[k];
        acc.x += s * wv.x; acc.y += s * wv.y;
        acc.z += s * wv.z; acc.w += s * wv.w;
    }
    ((float4*)(part + (size_t)(b * 8 + kc) * CM_STRIDE))[j4] = acc;
}

__global__ void cond_reduce_kernel(const float* __restrict__ part,
                                   const float* __restrict__ bmod,
                                   float* __restrict__ cm)
{
    int j4 = blockIdx.x * 256 + threadIdx.x;   // grid (6, 4)
    int b = blockIdx.y;
    float4 acc = ((const float4*)bmod)[j4];
    #pragma unroll
    for (int s = 0; s < 8; s++) {
        float4 p = ((const float4*)(part + (size_t)(b * 8 + s) * CM_STRIDE))[j4];
        acc.x += p.x; acc.y += p.y; acc.z += p.z; acc.w += p.w;
    }
    ((float4*)(cm + (size_t)b * CM_STRIDE))[j4] = acc;
}

// ------------------------- LayerNorm + modulate -> half (4 rows/CTA) --------
__global__ void ln_mod_h_kernel(const float* __restrict__ x,
                                const float* __restrict__ cm,
                                int shiftOff, int scaleOff,
                                __half* __restrict__ out)
{
    int tid = threadIdx.x;
    int sub = tid >> 6;           // 0..3: row within the quad
    int t = tid & 63;             // 64 threads per row
    int row = blockIdx.x * 4 + sub;
    int b = row >> 10;
    const float* xr = x + (size_t)row * Hdim;
    int col16 = t * 16;

    float4 u0 = *(const float4*)(xr + col16);
    float4 u1 = *(const float4*)(xr + col16 + 4);
    float4 u2 = *(const float4*)(xr + col16 + 8);
    float4 u3 = *(const float4*)(xr + col16 + 12);
    float s  = u0.x + u0.y + u0.z + u0.w + u1.x + u1.y + u1.z + u1.w
             + u2.x + u2.y + u2.z + u2.w + u3.x + u3.y + u3.z + u3.w;
    float sq = u0.x * u0.x + u0.y * u0.y + u0.z * u0.z + u0.w * u0.w
             + u1.x * u1.x + u1.y * u1.y + u1.z * u1.z + u1.w * u1.w
             + u2.x * u2.x + u2.y * u2.y + u2.z * u2.z + u2.w * u2.w
             + u3.x * u3.x + u3.y * u3.y + u3.z * u3.z + u3.w * u3.w;
    #pragma unroll
    for (int o = 16; o > 0; o >>= 1) {
        s  += __shfl_down_sync(0xffffffffu, s,  o);
        sq += __shfl_down_sync(0xffffffffu, sq, o);
    }
    __shared__ float red[24];
    int warp = tid >> 5, lane = tid & 31;
    if (lane == 0) { red[warp] = s; red[warp + 8] = sq; }
    __syncthreads();
    if (t == 0) {
        float S  = red[2 * sub] + red[2 * sub + 1];
        float SQ = red[2 * sub + 8] + red[2 * sub + 9];
        float mu = S * (1.0f / Hdim);
        float var = SQ * (1.0f / Hdim) - mu * mu;
        red[16 + 2 * sub] = mu;
        red[17 + 2 * sub] = rsqrtf(var + 1e-5f);
    }
    __syncthreads();
    float mu = red[16 + 2 * sub], inv = red[17 + 2 * sub];

    const float* sh = cm + b * CM_STRIDE + shiftOff;
    const float* sc = cm + b * CM_STRIDE + scaleOff;
    unsigned o8[8];
    #pragma unroll
    for (int q = 0; q < 4; q++) {
        float4 uv = (q == 0) ? u0 : (q == 1) ? u1 : (q == 2) ? u2 : u3;
        float4 shv = *(const float4*)(sh + col16 + q * 4);
        float4 scv = *(const float4*)(sc + col16 + q * 4);
        o8[2 * q + 0] = f2h2((uv.x - mu) * inv * (1.0f + scv.x) + shv.x,
                             (uv.y - mu) * inv * (1.0f + scv.y) + shv.y);
        o8[2 * q + 1] = f2h2((uv.z - mu) * inv * (1.0f + scv.z) + shv.z,
                             (uv.w - mu) * inv * (1.0f + scv.w) + shv.w);
    }
    *(uint4*)&out[(size_t)row * Hdim + col16]     = *(uint4*)&o8[0];
    *(uint4*)&out[(size_t)row * Hdim + col16 + 8] = *(uint4*)&o8[4];
}

// ------------------------- fp16 GEMM: 128x128, BK=64, 3-stage, 2 CTAs/SM ----
#define AW 36
#define BW 68
#define STAGE_U32 (128 * AW + 64 * BW)    // 8960
#define GSMEM2 (3 * STAGE_U32 * 4)        // 107520 bytes

template<int EPI>
__global__ __launch_bounds__(256, 2)
void gemm_h(const __half* __restrict__ A, const __half* __restrict__ Bh,
            const float* __restrict__ bias, void* __restrict__ Cout,
            int M, int N, int K,
            const float* __restrict__ gate, const float* __restrict__ resid)
{
    extern __shared__ unsigned sm[];
    int tid = threadIdx.x;
    int warp = tid >> 5, lane = tid & 31;
    int warpM = warp >> 2, warpN = warp & 3;
    int g = lane >> 2, r = lane & 3;
    int rowBase = blockIdx.y * 128, colBase = blockIdx.x * 128;
    int kts = K / 64;

    uint32_t smBase = smem_u32(sm);

    auto loadStage = [&](int stage, int kt) {
        uint32_t sA = smBase + stage * STAGE_U32 * 4;
        uint32_t sB = sA + 128 * AW * 4;
        const __half* Ag = A + (size_t)rowBase * K + kt * 64;
        const __half* Bg = Bh + (size_t)(kt * 64) * N + colBase;
        #pragma unroll
        for (int i = 0; i < 4; i++) {
            int j = tid + i * 256;
            int row = j >> 3, seg = j & 7;
            CP_ASYNC16(sA + row * 144 + seg * 16, Ag + (size_t)row * K + seg * 8);
        }
        #pragma unroll
        for (int i = 0; i < 4; i++) {
            int j = tid + i * 256;
            int row = j >> 4, seg = j & 15;
            CP_ASYNC16(sB + row * 272 + seg * 16, Bg + (size_t)row * N + seg * 8);
        }
    };

    float acc[4][4][4] = {};

    loadStage(0, 0); CP_COMMIT();
    loadStage(1, 1); CP_COMMIT();

    int lrow = lane & 15, lhi = lane >> 4;

    for (int kt = 0; kt < kts; kt++) {
        CP_WAIT1();
        __syncthreads();
        if (kt + 2 < kts) loadStage((kt + 2) % 3, kt + 2);
        CP_COMMIT();

        uint32_t sA = smBase + (kt % 3) * STAGE_U32 * 4;
        uint32_t sB = sA + 128 * AW * 4;
        #pragma unroll
        for (int ks = 0; ks < 4; ks++) {
            unsigned af[4][4], bf[4][2];
            #pragma unroll
            for (int mi = 0; mi < 4; mi++) {
                uint32_t a = sA + ((warpM * 64 + mi * 16 + lrow) * AW
                                   + ks * 8 + lhi * 4) * 4;
                LDSM4(af[mi][0], af[mi][1], af[mi][2], af[mi][3], a);
            }
            #pragma unroll
            for (int p = 0; p < 2; p++) {
                uint32_t bAddr = sB + ((ks * 16 + lrow) * BW
                                       + warpN * 16 + p * 8 + lhi * 4) * 4;
                LDSM4T(bf[2 * p][0], bf[2 * p][1], bf[2 * p + 1][0], bf[2 * p + 1][1], bAddr);
            }
            #pragma unroll
            for (int mi = 0; mi < 4; mi++)
                #pragma unroll
                for (int nj = 0; nj < 4; nj++)
                    mma_f16(acc[mi][nj], af[mi], bf[nj]);
        }
    }

    #pragma unroll
    for (int mi = 0; mi < 4; mi++) {
        #pragma unroll
        for (int rr = 0; rr < 2; rr++) {
            int row = rowBase + warpM * 64 + mi * 16 + g + rr * 8;
            int b = row >> 10;
            #pragma unroll
            for (int nj = 0; nj < 4; nj++) {
                int col = colBase + warpN * 32 + nj * 8 + r * 2;
                float v0 = acc[mi][nj][rr * 2 + 0] + __ldg(&bias[col]);
                float v1 = acc[mi][nj][rr * 2 + 1] + __ldg(&bias[col + 1]);
                if (EPI == 0) {
                    float sc = (col < Hdim) ? 0.125f : 1.0f;
                    __half* Ch = (__half*)Cout;
                    *(unsigned*)&Ch[(size_t)row * N + col] = f2h2(v0 * sc, v1 * sc);
                } else if (EPI == 1) {
                    v0 = 0.5f * v0 * (1.0f + erff(v0 * 0.70710678118654752f));
                    v1 = 0.5f * v1 * (1.0f + erff(v1 * 0.70710678118654752f));
                    __half* Ch = (__half*)Cout;
                    *(unsigned*)&Ch[(size_t)row * N + col] = f2h2(v0, v1);
                } else if (EPI == 2) {
                    v0 *= (1.0f + __ldg(&gate[b * CM_STRIDE + col]));
                    v1 *= (1.0f + __ldg(&gate[b * CM_STRIDE + col + 1]));
                    *(float2*)&((float*)Cout)[(size_t)row * N + col] = make_float2(v0, v1);
                } else {
                    v0 = resid[(size_t)row * N + col]     + __ldg(&gate[b * CM_STRIDE + col])     * v0;
                    v1 = resid[(size_t)row * N + col + 1] + __ldg(&gate[b * CM_STRIDE + col + 1]) * v1;
                    *(float2*)&((float*)Cout)[(size_t)row * N + col] = make_float2(v0, v1);
                }
            }
        }
    }
}

// ------------------------- flash attention (reg P, LDSM K/V) ----------------
#define PSTR2 36
#define KVW 36
#define FPS_U32 (128 * PSTR2)
#define FKV_U32 (64 * KVW)
#define FSMEM ((FPS_U32 + 6 * FKV_U32) * 4)   // 73728 bytes

__global__ __launch_bounds__(256, 2)
void flash_attn(const __half* __restrict__ qkv, __half* __restrict__ out)
{
    extern __shared__ unsigned fsm[];
    unsigned* Ps2 = fsm;
    uint32_t psBase = smem_u32(fsm);
    uint32_t kBase = psBase + FPS_U32 * 4;
    uint32_t vBase = kBase + 3 * FKV_U32 * 4;

    int tid = threadIdx.x;
    int warp = tid >> 5, lane = tid & 31;
    int g = lane >> 2, r = lane & 3;
    int lrow = lane & 15, lhi = lane >> 4;
    int bh = blockIdx.y;
    int b = bh >> 4, h = bh & 15;
    int q0 = blockIdx.x * 128;

    const int NIT = Ntok / 64;

    auto loadKV = [&](int s, int n0) {
        uint32_t kS = kBase + s * FKV_U32 * 4;
        uint32_t vS = vBase + s * FKV_U32 * 4;
        #pragma unroll
        for (int i = 0; i < 2; i++) {
            int j = tid + i * 256;
            int key = j >> 3, seg = j & 7;
            const __half* kp = qkv + (size_t)(b * Ntok + n0 + key) * 3 * Hdim
                               + Hdim + h * HD + seg * 8;
            CP_ASYNC16(kS + key * 144 + seg * 16, kp);
            CP_ASYNC16(vS + key * 144 + seg * 16, kp + Hdim);
        }
    };

    loadKV(0, 0); CP_COMMIT();
    loadKV(1, 64); CP_COMMIT();

    #pragma unroll
    for (int i = 0; i < 4; i++) {
        int j = tid + i * 256;
        int row = j >> 3, d8 = (j & 7) * 8;
        uint4 v = *(const uint4*)(qkv + (size_t)(b * Ntok + q0 + row) * 3 * Hdim
                                  + h * HD + d8);
        *(uint4*)&Ps2[row * PSTR2 + (j & 7) * 4] = v;
    }
    __syncthreads();

    int qrow = warp * 16 + g;
    unsigned qf[4][4];
    #pragma unroll
    for (int ks = 0; ks < 4; ks++) {
        qf[ks][0] = Ps2[qrow * PSTR2 + ks * 8 + r];
        qf[ks][1] = Ps2[(qrow + 8) * PSTR2 + ks * 8 + r];
        qf[ks][2] = Ps2[qrow * PSTR2 + ks * 8 + r + 4];
        qf[ks][3] = Ps2[(qrow + 8) * PSTR2 + ks * 8 + r + 4];
    }

    int kgrp = lane >> 3, krow = lane & 7;

    float oacc[8][4] = {};
    float m0 = -1e30f, m1 = -1e30f, l0 = 0.0f, l1 = 0.0f;

    for (int it = 0; it < NIT; it++) {
        int s = it % 3;
        CP_WAIT1();
        __syncthreads();
        if (it + 2 < NIT) loadKV((it + 2) % 3, (it + 2) * 64);
        CP_COMMIT();

        uint32_t kS = kBase + s * FKV_U32 * 4;
        uint32_t vS = vBase + s * FKV_U32 * 4;

        // ---- S = Q K^T (K fragments via ldmatrix.x4 non-trans) ----
        float sacc[8][4] = {};
        #pragma unroll
        for (int ks = 0; ks < 4; ks++) {
            #pragma unroll
            for (int njp = 0; njp < 4; njp++) {
                int nj = njp * 2 + (kgrp >> 1);
                int key = nj * 8 + krow;
                uint32_t kaddr = kS + key * 144 + (ks * 8 + (kgrp & 1) * 4) * 4;
                unsigned b0, b1, b2, b3;
                LDSM4(b0, b1, b2, b3, kaddr);
                unsigned bf0[2] = {b0, b1}, bf1[2] = {b2, b3};
                mma_f16(sacc[njp * 2 + 0], qf[ks], bf0);
                mma_f16(sacc[njp * 2 + 1], qf[ks], bf1);
            }
        }

        // ---- online softmax, P packed into mma A-fragments ----
        float mc0 = -1e30f, mc1 = -1e30f;
        #pragma unroll
        for (int nj = 0; nj < 8; nj++) {
            mc0 = fmaxf(mc0, fmaxf(sacc[nj][0], sacc[nj][1]));
            mc1 = fmaxf(mc1, fmaxf(sacc[nj][2], sacc[nj][3]));
        }
        mc0 = fmaxf(mc0, __shfl_xor_sync(0xffffffffu, mc0, 1));
        mc0 = fmaxf(mc0, __shfl_xor_sync(0xffffffffu, mc0, 2));
        mc1 = fmaxf(mc1, __shfl_xor_sync(0xffffffffu, mc1, 1));
        mc1 = fmaxf(mc1, __shfl_xor_sync(0xffffffffu, mc1, 2));
        float mn0 = fmaxf(m0, mc0), mn1 = fmaxf(m1, mc1);
        float a0 = __expf(m0 - mn0), a1 = __expf(m1 - mn1);
        float rs0 = 0.0f, rs1 = 0.0f;
        unsigned ph[8][2];
        #pragma unroll
        for (int nj = 0; nj < 8; nj++) {
            float p0 = __expf(sacc[nj][0] - mn0);
            float p1 = __expf(sacc[nj][1] - mn0);
            float p2 = __expf(sacc[nj][2] - mn1);
            float p3 = __expf(sacc[nj][3] - mn1);
            rs0 += p0 + p1; rs1 += p2 + p3;
            ph[nj][0] = f2h2(p0, p1);
            ph[nj][1] = f2h2(p2, p3);
        }
        rs0 += __shfl_xor_sync(0xffffffffu, rs0, 1);
        rs0 += __shfl_xor_sync(0xffffffffu, rs0, 2);
        rs1 += __shfl_xor_sync(0xffffffffu, rs1, 1);
        rs1 += __shfl_xor_sync(0xffffffffu, rs1, 2);
        l0 = l0 * a0 + rs0;
        l1 = l1 * a1 + rs1;
        m0 = mn0; m1 = mn1;
        #pragma unroll
        for (int nj = 0; nj < 8; nj++) {
            oacc[nj][0] *= a0; oacc[nj][1] *= a0;
            oacc[nj][2] *= a1; oacc[nj][3] *= a1;
        }

        // ---- O += P V  (P registers, V via LDSM4T) ----
        #pragma unroll
        for (int ks = 0; ks < 4; ks++) {
            unsigned af[4], bf[8][2];
            af[0] = ph[2 * ks][0];
            af[1] = ph[2 * ks][1];
            af[2] = ph[2 * ks + 1][0];
            af[3] = ph[2 * ks + 1][1];
            #pragma unroll
            for (int p = 0; p < 4; p++) {
                uint32_t vAddr = vS + ((ks * 16 + lrow) * KVW + p * 8 + lhi * 4) * 4;
                LDSM4T(bf[2 * p][0], bf[2 * p][1], bf[2 * p + 1][0], bf[2 * p + 1][1], vAddr);
            }
            #pragma unroll
            for (int nj = 0; nj < 8; nj++)
                mma_f16(oacc[nj], af, bf[nj]);
        }
    }

    float i0 = 1.0f / l0, i1 = 1.0f / l1;
    #pragma unroll
    for (int nj = 0; nj < 8; nj++) {
        int col = h * HD + nj * 8 + 2 * r;
        *(unsigned*)&out[(size_t)(b * Ntok + q0 + qrow) * Hdim + col]
            = f2h2(oacc[nj][0] * i0, oacc[nj][1] * i0);
        *(unsigned*)&out[(size_t)(b * Ntok + q0 + qrow + 8) * Hdim + col]
            = f2h2(oacc[nj][2] * i1, oacc[nj][3] * i1);
    }
}

// ------------------------- launch ------------------------------------------
extern "C" void kernel_launch(void* const* d_in, const int* in_sizes, int n_in,
                              void* d_out, int out_size)
{
    const float* x      = (const float*)d_in[0];
    const float* c      = (const float*)d_in[1];
    const float* w_mod  = (const float*)d_in[2];
    const float* b_mod  = (const float*)d_in[3];
    const float* w_qkv  = (const float*)d_in[4];
    const float* b_qkv  = (const float*)d_in[5];
    const float* w_proj = (const float*)d_in[6];
    const float* b_proj = (const float*)d_in[7];
    const float* w1     = (const float*)d_in[8];
    const float* b1     = (const float*)d_in[9];
    const float* w2     = (const float*)d_in[10];
    const float* b2     = (const float*)d_in[11];
    float* out = (float*)d_out;

    float *cm, *cpart, *x2;
    __half *xmh, *qkvh, *attnh, *xm2h, *hidh, *wqkvH, *w1H, *w2H, *wpH;
    cudaGetSymbolAddress((void**)&cm,    g_cm);
    cudaGetSymbolAddress((void**)&cpart, g_cpart);
    cudaGetSymbolAddress((void**)&xmh,   g_xmh);
    cudaGetSymbolAddress((void**)&qkvh,  g_qkvh);
    cudaGetSymbolAddress((void**)&attnh, g_attnh);
    cudaGetSymbolAddress((void**)&x2,    g_x2);
    cudaGetSymbolAddress((void**)&xm2h,  g_xm2h);
    cudaGetSymbolAddress((void**)&hidh,  g_hidh);
    cudaGetSymbolAddress((void**)&wqkvH, g_wqkvH);
    cudaGetSymbolAddress((void**)&w1H,   g_w1H);
    cudaGetSymbolAddress((void**)&w2H,   g_w2H);
    cudaGetSymbolAddress((void**)&wpH,   g_wpH);

    cudaFuncSetAttribute(gemm_h<0>, cudaFuncAttributeMaxDynamicSharedMemorySize, GSMEM2);
    cudaFuncSetAttribute(gemm_h<1>, cudaFuncAttributeMaxDynamicSharedMemorySize, GSMEM2);
    cudaFuncSetAttribute(gemm_h<2>, cudaFuncAttributeMaxDynamicSharedMemorySize, GSMEM2);
    cudaFuncSetAttribute(gemm_h<3>, cudaFuncAttributeMaxDynamicSharedMemorySize, GSMEM2);
    cudaFuncSetAttribute(flash_attn, cudaFuncAttributeMaxDynamicSharedMemorySize, FSMEM);

    // 0. all weight conversions, one kernel, 2 float4s per thread
    whalf_all_kernel<<<HALF_F4 / 256, 256>>>(
        w_qkv, w1, w2, w_proj, wqkvH, w1H, w2H, wpH);

    // 1. conditioning -> modulation params (split-K, float4)
    cond_part_kernel<<<dim3(6, 4, 8), 256>>>(c, w_mod, cpart);
    cond_reduce_kernel<<<dim3(6, 4), 256>>>(cpart, b_mod, cm);

    // 2. LN + modulate (msa) -> half
    ln_mod_h_kernel<<<ROWS / 4, 256>>>(x, cm, 0, Hdim, xmh);

    // 3. qkv (half out, Q pre-scaled by 1/8)
    gemm_h<0><<<dim3(3 * Hdim / 128, ROWS / 128), 256, GSMEM2>>>(
        xmh, wqkvH, b_qkv, qkvh, ROWS, 3 * Hdim, Hdim, nullptr, nullptr);

    // 4. flash attention -> half attnout
    flash_attn<<<dim3(Ntok / 128, Bsz * NH), 256, FSMEM>>>(qkvh, attnh);

    // 5. x2 = (attnout @ w_proj + b_proj) * (1 + gate_msa)   (float out)
    gemm_h<2><<<dim3(Hdim / 128, ROWS / 128), 256, GSMEM2>>>(
        attnh, wpH, b_proj, x2, ROWS, Hdim, Hdim, cm + 2 * Hdim, nullptr);

    // 6. LN + modulate (mlp) -> half
    ln_mod_h_kernel<<<ROWS / 4, 256>>>(x2, cm, 3 * Hdim, 4 * Hdim, xm2h);

    // 7. hid = gelu(xm2 @ w1 + b1)  (half out)
    gemm_h<1><<<dim3(DFF / 128, ROWS / 128), 256, GSMEM2>>>(
        xm2h, w1H, b1, hidh, ROWS, DFF, Hdim, nullptr, nullptr);

    // 8. out = x2 + gate_mlp * (hid @ w2 + b2)  (float out)
    gemm_h<3><<<dim3(Hdim / 128, ROWS / 128), 256, GSMEM2>>>(
        hidh, w2H, b2, out, ROWS, Hdim, DFF, cm + 5 * Hdim, x2);
}